// round 5
// baseline (speedup 1.0000x reference)
#include <cuda_runtime.h>
#include <cuda_fp16.h>
#include <cstdint>

// Problem constants
#define BN 32
#define LN 32768
#define DN 128
#define PN 4095   // (L-K)/STRIDE + 1

// ---------------------------------------------------------------------------
// Pre-packed B (fp16): [16 chunks][128 n][32 k] halfs, contiguous (64B/row).
// chunk t, row n (=d), col kk (=m): element = conv_w[n*512 + kk*16 + t]
// ---------------------------------------------------------------------------
__device__ __half g_Bh[16 * 128 * 32];   // 128 KB

__global__ void pack_w_kernel(const float* __restrict__ w) {
    int idx = blockIdx.x * blockDim.x + threadIdx.x;  // 0..65535
    int t  = idx >> 12;
    int n  = (idx >> 5) & 127;
    int kk = idx & 31;
    g_Bh[idx] = __float2half_rn(w[n * 512 + kk * 16 + t]);
}

__device__ __forceinline__ uint32_t pack_h2(float x, float y) {
    uint32_t r;
    asm("{ .reg .f16 lo, hi;\n\t"
        "cvt.rn.f16.f32 lo, %1;\n\t"
        "cvt.rn.f16.f32 hi, %2;\n\t"
        "mov.b32 %0, {lo, hi}; }"
        : "=r"(r) : "f"(x), "f"(y));
    return r;
}

__device__ __forceinline__ void mma_f16(float c[4], const uint32_t a[4],
                                        uint32_t b0, uint32_t b1) {
    asm volatile(
        "mma.sync.aligned.m16n8k16.row.col.f32.f16.f16.f32 "
        "{%0,%1,%2,%3}, {%4,%5,%6,%7}, {%8,%9}, {%0,%1,%2,%3};\n"
        : "+f"(c[0]), "+f"(c[1]), "+f"(c[2]), "+f"(c[3])
        : "r"(a[0]), "r"(a[1]), "r"(a[2]), "r"(a[3]), "r"(b0), "r"(b1));
}

#define LDMATRIX_X4(r, addr)                                                  \
    asm volatile("ldmatrix.sync.aligned.m8n8.x4.shared.b16 {%0,%1,%2,%3}, [%4];" \
                 : "=r"((r)[0]), "=r"((r)[1]), "=r"((r)[2]), "=r"((r)[3])     \
                 : "r"(addr))

__device__ __forceinline__ uint32_t smem_u32(const void* p) {
    uint32_t a;
    asm("{ .reg .u64 t; cvta.to.shared.u64 t, %1; cvt.u32.u64 %0, t; }"
        : "=r"(a) : "l"(p));
    return a;
}

// SMEM tiles: rows padded to 40 halfs (80 B) -> conflict-free ldmatrix phases
#define ROWB 80
#define TILEB (128 * ROWB)   // 10240 B per stage

// CTA: 128 patches x 128 D, 256 threads = 8 warps, warp tile 32(m) x 64(n).
// K = 512 in 16 chunks of 32, double-buffered pipeline.
__global__ __launch_bounds__(256, 2) void patch_encoder_kernel(
    const float* __restrict__ x,     // (B, L, M)
    const float* __restrict__ ts,    // (B, L)
    const float* __restrict__ bias,  // (D,)
    float* __restrict__ out)         // (B, P, D)
{
    __shared__ __align__(16) unsigned char Abuf[2][TILEB];
    __shared__ __align__(16) unsigned char Bbuf[2][TILEB];
    __shared__ float meds[128];
    __shared__ float sbias[128];
    __shared__ float sdiv[64];

    const int tid  = threadIdx.x;
    const int b    = blockIdx.y;
    const int p0   = blockIdx.x * 128;
    const int wid  = tid >> 5;
    const int lane = tid & 31;
    const int wm   = wid & 3;     // m offset wm*32
    const int wn   = wid >> 2;    // n offset wn*64
    const int g    = lane >> 2;
    const int q    = lane & 3;

    if (tid < 128) {
        int p = p0 + tid;
        meds[tid]  = (p < PN) ? ts[(size_t)b * LN + p * 8 + 7] : 0.0f;
        sbias[tid] = bias[tid];
    }
    if (tid < 64)
        sdiv[tid] = expf((float)(2 * tid) * -0.07195578800731849f);

    float acc[2][8][4];
#pragma unroll
    for (int mf = 0; mf < 2; mf++)
#pragma unroll
        for (int nf = 0; nf < 8; nf++)
#pragma unroll
            for (int i = 0; i < 4; i++) acc[mf][nf][i] = 0.0f;

    const float* xbase = x + ((size_t)b * LN + (size_t)p0 * 8) * 32;
    const char*  gB    = (const char*)g_Bh;

    // per-thread tile-load coords: 512 16B-slots, 2 per thread
    const int r0 = tid >> 2;
    const int j0 = tid & 3;
    const int r1 = (256 + tid) >> 2;
    const int j1 = tid & 3;

    float4 va[2][2];

#define LOAD_A(t_)                                                            \
    do {                                                                      \
        va[0][0] = make_float4(0.f, 0.f, 0.f, 0.f);                           \
        va[0][1] = va[0][0]; va[1][0] = va[0][0]; va[1][1] = va[0][0];        \
        if (p0 + r0 < PN) {                                                   \
            const float* s = xbase + ((size_t)r0 * 8 + (t_)) * 32 + j0 * 8;   \
            va[0][0] = *(const float4*)s;                                     \
            va[0][1] = *(const float4*)(s + 4);                               \
        }                                                                     \
        if (p0 + r1 < PN) {                                                   \
            const float* s = xbase + ((size_t)r1 * 8 + (t_)) * 32 + j1 * 8;   \
            va[1][0] = *(const float4*)s;                                     \
            va[1][1] = *(const float4*)(s + 4);                               \
        }                                                                     \
    } while (0)

#define CPASYNC_B(t_, buf_)                                                   \
    do {                                                                      \
        uint32_t d0 = smem_u32(&Bbuf[buf_][r0 * ROWB + j0 * 16]);             \
        uint32_t d1 = smem_u32(&Bbuf[buf_][r1 * ROWB + j1 * 16]);             \
        const char* s0 = gB + (t_) * 8192 + r0 * 64 + j0 * 16;                \
        const char* s1 = gB + (t_) * 8192 + r1 * 64 + j1 * 16;                \
        asm volatile("cp.async.ca.shared.global [%0], [%1], 16;" :: "r"(d0), "l"(s0)); \
        asm volatile("cp.async.ca.shared.global [%0], [%1], 16;" :: "r"(d1), "l"(s1)); \
        asm volatile("cp.async.commit_group;");                               \
    } while (0)

#define STS_A(buf_)                                                           \
    do {                                                                      \
        uint32_t d0 = smem_u32(&Abuf[buf_][r0 * ROWB + j0 * 16]);             \
        uint32_t d1 = smem_u32(&Abuf[buf_][r1 * ROWB + j1 * 16]);             \
        uint32_t h0 = pack_h2(va[0][0].x, va[0][0].y);                        \
        uint32_t h1 = pack_h2(va[0][0].z, va[0][0].w);                        \
        uint32_t h2 = pack_h2(va[0][1].x, va[0][1].y);                        \
        uint32_t h3 = pack_h2(va[0][1].z, va[0][1].w);                        \
        asm volatile("st.shared.v4.b32 [%0], {%1,%2,%3,%4};"                  \
                     :: "r"(d0), "r"(h0), "r"(h1), "r"(h2), "r"(h3));         \
        h0 = pack_h2(va[1][0].x, va[1][0].y);                                 \
        h1 = pack_h2(va[1][0].z, va[1][0].w);                                 \
        h2 = pack_h2(va[1][1].x, va[1][1].y);                                 \
        h3 = pack_h2(va[1][1].z, va[1][1].w);                                 \
        asm volatile("st.shared.v4.b32 [%0], {%1,%2,%3,%4};"                  \
                     :: "r"(d1), "r"(h0), "r"(h1), "r"(h2), "r"(h3));         \
    } while (0)

    // ---- prologue: tile 0 ----
    LOAD_A(0);
    CPASYNC_B(0, 0);
    STS_A(0);
    asm volatile("cp.async.wait_group 0;" ::: "memory");
    __syncthreads();

    // ---- ldmatrix per-lane fragment addresses ----
    // A: lanes 0-7 -> m rows 0-7 (k-lo), 8-15 -> m 8-15 (k-lo),
    //    16-23 -> m 0-7 (k-hi +16B), 24-31 -> m 8-15 (k-hi)   == a0..a3
    const uint32_t aFragBase = smem_u32(&Abuf[0][0]) +
        (uint32_t)((wm * 32 + (lane & 15)) * ROWB + (lane >> 4) * 16);
    // B: lanes 0-7 -> n rows 0-7 k-lo (b0 even nf), 8-15 -> n 0-7 k-hi (b1),
    //    16-23 -> n 8-15 k-lo (b0 odd nf), 24-31 -> n 8-15 k-hi (b1)
    const uint32_t bFragBase = smem_u32(&Bbuf[0][0]) +
        (uint32_t)((wn * 64 + (lane & 7) + ((lane >> 4) << 3)) * ROWB +
                   ((lane >> 3) & 1) * 16);

    for (int t = 0; t < 16; t++) {
        const int cur = t & 1;
        const int nxt = cur ^ 1;

        if (t < 15) {
            LOAD_A(t + 1);
            CPASYNC_B(t + 1, nxt);
        }

        // ---- compute: 2 k16-steps, ldmatrix fragments + 16 mmas ----
#pragma unroll
        for (int ks = 0; ks < 2; ks++) {
            uint32_t a[2][4];
            LDMATRIX_X4(a[0], aFragBase + cur * TILEB + ks * 32);
            LDMATRIX_X4(a[1], aFragBase + cur * TILEB + 16 * ROWB + ks * 32);
            uint32_t bb[4][4];
#pragma unroll
            for (int nb = 0; nb < 4; nb++)
                LDMATRIX_X4(bb[nb], bFragBase + cur * TILEB + nb * (16 * ROWB) + ks * 32);
#pragma unroll
            for (int nf = 0; nf < 8; nf++) {
                uint32_t b0 = bb[nf >> 1][(nf & 1) * 2];
                uint32_t b1 = bb[nf >> 1][(nf & 1) * 2 + 1];
                mma_f16(acc[0][nf], a[0], b0, b1);
                mma_f16(acc[1][nf], a[1], b0, b1);
            }
        }

        if (t < 15) {
            STS_A(nxt);
            asm volatile("cp.async.wait_group 0;" ::: "memory");
        }
        __syncthreads();
    }

    // ---- epilogue: + bias + positional encoding (fast sincos), write out ----
#pragma unroll
    for (int mf = 0; mf < 2; mf++) {
        int rr0 = wm * 32 + mf * 16 + g;
        int rr1 = rr0 + 8;
        float med0 = meds[rr0];
        float med1 = meds[rr1];
        bool ok0 = (p0 + rr0) < PN;
        bool ok1 = (p0 + rr1) < PN;
        size_t base0 = ((size_t)b * PN + (size_t)(p0 + rr0)) * DN;
        size_t base1 = ((size_t)b * PN + (size_t)(p0 + rr1)) * DN;
#pragma unroll
        for (int nf = 0; nf < 8; nf++) {
            int col = wn * 64 + nf * 8 + 2 * q;   // even
            float dv = sdiv[col >> 1];
            float bs0 = sbias[col];
            float bs1 = sbias[col + 1];
            float s, c;
            if (ok0) {
                __sincosf(med0 * dv, &s, &c);
                float2 v;
                v.x = (mf ? acc[1][nf][0] : acc[0][nf][0]) + bs0 + s;
                v.y = (mf ? acc[1][nf][1] : acc[0][nf][1]) + bs1 + c;
                *(float2*)(out + base0 + col) = v;
            }
            if (ok1) {
                __sincosf(med1 * dv, &s, &c);
                float2 v;
                v.x = (mf ? acc[1][nf][2] : acc[0][nf][2]) + bs0 + s;
                v.y = (mf ? acc[1][nf][3] : acc[0][nf][3]) + bs1 + c;
                *(float2*)(out + base1 + col) = v;
            }
        }
    }
}

extern "C" void kernel_launch(void* const* d_in, const int* in_sizes, int n_in,
                              void* d_out, int out_size) {
    const float* x    = (const float*)d_in[0];
    const float* ts   = (const float*)d_in[1];
    const float* w    = (const float*)d_in[2];
    const float* bias = (const float*)d_in[3];
    float* out = (float*)d_out;

    pack_w_kernel<<<256, 256>>>(w);

    dim3 grid(32, BN);   // 32 patch-tiles x 32 batches
    patch_encoder_kernel<<<grid, 256>>>(x, ts, bias, out);
}

// round 6
// speedup vs baseline: 1.3454x; 1.3454x over previous
#include <cuda_runtime.h>
#include <cuda_fp16.h>
#include <cstdint>

// Problem constants
#define BN 32
#define LN 32768
#define DN 128
#define PN 4095   // (L-K)/STRIDE + 1

// ---------------------------------------------------------------------------
// Pre-packed B (fp16): [16 chunks][128 n][32 k] halfs, contiguous (64B/row).
// chunk t, row n (=d), col kk (=m): element = conv_w[n*512 + kk*16 + t]
// ---------------------------------------------------------------------------
__device__ __half g_Bh[16 * 128 * 32];   // 128 KB

__global__ void pack_w_kernel(const float* __restrict__ w) {
    int idx = blockIdx.x * blockDim.x + threadIdx.x;  // 0..65535
    int t  = idx >> 12;
    int n  = (idx >> 5) & 127;
    int kk = idx & 31;
    g_Bh[idx] = __float2half_rn(w[n * 512 + kk * 16 + t]);
}

__device__ __forceinline__ uint32_t pack_h2(float x, float y) {
    uint32_t r;
    asm("{ .reg .f16 lo, hi;\n\t"
        "cvt.rn.f16.f32 lo, %1;\n\t"
        "cvt.rn.f16.f32 hi, %2;\n\t"
        "mov.b32 %0, {lo, hi}; }"
        : "=r"(r) : "f"(x), "f"(y));
    return r;
}

__device__ __forceinline__ void mma_f16(float c[4], const uint32_t a[4],
                                        uint32_t b0, uint32_t b1) {
    asm volatile(
        "mma.sync.aligned.m16n8k16.row.col.f32.f16.f16.f32 "
        "{%0,%1,%2,%3}, {%4,%5,%6,%7}, {%8,%9}, {%0,%1,%2,%3};\n"
        : "+f"(c[0]), "+f"(c[1]), "+f"(c[2]), "+f"(c[3])
        : "r"(a[0]), "r"(a[1]), "r"(a[2]), "r"(a[3]), "r"(b0), "r"(b1));
}

__device__ __forceinline__ uint32_t smem_u32(const void* p) {
    uint32_t a;
    asm("{ .reg .u64 t; cvta.to.shared.u64 t, %1; cvt.u32.u64 %0, t; }"
        : "=r"(a) : "l"(p));
    return a;
}

// SMEM tiles: rows padded to 40 halfs (80 B) -> conflict-free fragment LDS
#define ROWB 80
#define TILEB (128 * ROWB)   // 10240 B per stage
#define NBSTG 4              // B ring depth

// CTA: 128 patches x 128 D, 128 threads = 4 warps, warp tile 64(m) x 64(n).
// K = 512 in 16 chunks of 32.  A double-buffered, B 4-stage cp.async ring.
__global__ __launch_bounds__(128, 2) void patch_encoder_kernel(
    const float* __restrict__ x,     // (B, L, M)
    const float* __restrict__ ts,    // (B, L)
    const float* __restrict__ bias,  // (D,)
    float* __restrict__ out)         // (B, P, D)
{
    __shared__ __align__(16) unsigned char Abuf[2][TILEB];
    __shared__ __align__(16) unsigned char Bbuf[NBSTG][TILEB];
    __shared__ float meds[128];
    __shared__ float sbias[128];
    __shared__ float sdiv[64];

    const int tid  = threadIdx.x;
    const int b    = blockIdx.y;
    const int p0   = blockIdx.x * 128;
    const int wid  = tid >> 5;
    const int lane = tid & 31;
    const int wm   = wid & 1;     // m offset wm*64
    const int wn   = wid >> 1;    // n offset wn*64
    const int g    = lane >> 2;
    const int q    = lane & 3;

    if (tid < 128) {
        int p = p0 + tid;
        meds[tid]  = (p < PN) ? ts[(size_t)b * LN + p * 8 + 7] : 0.0f;
        sbias[tid] = bias[tid];
    }
    if (tid < 64)
        sdiv[tid] = expf((float)(2 * tid) * -0.07195578800731849f);

    float acc[4][8][4];
#pragma unroll
    for (int mf = 0; mf < 4; mf++)
#pragma unroll
        for (int nf = 0; nf < 8; nf++)
#pragma unroll
            for (int i = 0; i < 4; i++) acc[mf][nf][i] = 0.0f;

    const float* xbase = x + ((size_t)b * LN + (size_t)p0 * 8) * 32;
    const char*  gB    = (const char*)g_Bh;

    // A load: 1024 float4 slots / 128 threads = 8 per thread.
    // slot s = it*128 + tid: row r = it*16 + (tid>>3), j = tid&7
    const int ar = tid >> 3;     // row sub-index
    const int aj = tid & 7;      // float4 within 32-float row

    float4 va[8];

#define LOAD_A(t_)                                                            \
    do {                                                                      \
        _Pragma("unroll")                                                     \
        for (int it = 0; it < 8; it++) {                                      \
            int r = it * 16 + ar;                                             \
            va[it] = make_float4(0.f, 0.f, 0.f, 0.f);                         \
            if (p0 + r < PN)                                                  \
                va[it] = *(const float4*)(xbase + ((size_t)r * 8 + (t_)) * 32 + aj * 4); \
        }                                                                     \
    } while (0)

#define STS_A(buf_)                                                           \
    do {                                                                      \
        _Pragma("unroll")                                                     \
        for (int it = 0; it < 8; it++) {                                      \
            int r = it * 16 + ar;                                             \
            uint32_t d = smem_u32(&Abuf[buf_][r * ROWB + aj * 8]);            \
            uint32_t h0 = pack_h2(va[it].x, va[it].y);                        \
            uint32_t h1 = pack_h2(va[it].z, va[it].w);                        \
            asm volatile("st.shared.v2.b32 [%0], {%1,%2};"                    \
                         :: "r"(d), "r"(h0), "r"(h1));                        \
        }                                                                     \
    } while (0)

    // B load: 512 16B slots / 128 threads = 4 per thread
#define CPASYNC_B(t_, st_)                                                    \
    do {                                                                      \
        _Pragma("unroll")                                                     \
        for (int i = 0; i < 4; i++) {                                         \
            int slot = i * 128 + tid;                                         \
            int r = slot >> 2, j = slot & 3;                                  \
            uint32_t d = smem_u32(&Bbuf[st_][r * ROWB + j * 16]);             \
            const char* s = gB + (t_) * 8192 + r * 64 + j * 16;               \
            asm volatile("cp.async.ca.shared.global [%0], [%1], 16;"          \
                         :: "r"(d), "l"(s));                                  \
        }                                                                     \
        asm volatile("cp.async.commit_group;");                               \
    } while (0)

    // ---- prologue: A tile 0; B groups 0,1,2 in flight ----
    LOAD_A(0);
    CPASYNC_B(0, 0);
    CPASYNC_B(1, 1);
    CPASYNC_B(2, 2);
    STS_A(0);
    asm volatile("cp.async.wait_group 2;" ::: "memory");
    __syncthreads();

    const uint32_t aBase = smem_u32(&Abuf[0][0]) + (wm * 64 + g) * ROWB + q * 4;
    const uint32_t bBase = smem_u32(&Bbuf[0][0]) + (wn * 64 + g) * ROWB + q * 4;

    for (int t = 0; t < 16; t++) {
        if (t < 15) LOAD_A(t + 1);
        if (t + 3 < 16) CPASYNC_B(t + 3, (t + 3) & (NBSTG - 1));

        const uint32_t aB = aBase + (t & 1) * TILEB;
        const uint32_t bB = bBase + (t & (NBSTG - 1)) * TILEB;
#pragma unroll
        for (int ks = 0; ks < 2; ks++) {
            uint32_t a[4][4];
#pragma unroll
            for (int mf = 0; mf < 4; mf++) {
                uint32_t ad = aB + mf * (16 * ROWB) + ks * 32;
                asm volatile("ld.shared.b32 %0, [%1];"       : "=r"(a[mf][0]) : "r"(ad));
                asm volatile("ld.shared.b32 %0, [%1+640];"   : "=r"(a[mf][1]) : "r"(ad));
                asm volatile("ld.shared.b32 %0, [%1+16];"    : "=r"(a[mf][2]) : "r"(ad));
                asm volatile("ld.shared.b32 %0, [%1+656];"   : "=r"(a[mf][3]) : "r"(ad));
            }
#pragma unroll
            for (int nf = 0; nf < 8; nf++) {
                uint32_t bd = bB + nf * (8 * ROWB) + ks * 32;
                uint32_t b0, b1;
                asm volatile("ld.shared.b32 %0, [%1];"    : "=r"(b0) : "r"(bd));
                asm volatile("ld.shared.b32 %0, [%1+16];" : "=r"(b1) : "r"(bd));
#pragma unroll
                for (int mf = 0; mf < 4; mf++)
                    mma_f16(acc[mf][nf], a[mf], b0, b1);
            }
        }

        if (t < 15) STS_A((t + 1) & 1);
        asm volatile("cp.async.wait_group 2;" ::: "memory");
        __syncthreads();
    }

    // ---- epilogue: + bias + positional encoding (fast sincos), write out ----
#pragma unroll
    for (int mf = 0; mf < 4; mf++) {
        int rr0 = wm * 64 + mf * 16 + g;
        int rr1 = rr0 + 8;
        float med0 = meds[rr0];
        float med1 = meds[rr1];
        bool ok0 = (p0 + rr0) < PN;
        bool ok1 = (p0 + rr1) < PN;
        size_t base0 = ((size_t)b * PN + (size_t)(p0 + rr0)) * DN;
        size_t base1 = ((size_t)b * PN + (size_t)(p0 + rr1)) * DN;
#pragma unroll
        for (int nf = 0; nf < 8; nf++) {
            int col = wn * 64 + nf * 8 + 2 * q;   // even
            float dv = sdiv[col >> 1];
            float bs0 = sbias[col];
            float bs1 = sbias[col + 1];
            float s, c;
            if (ok0) {
                __sincosf(med0 * dv, &s, &c);
                float2 v;
                v.x = acc[mf][nf][0] + bs0 + s;
                v.y = acc[mf][nf][1] + bs1 + c;
                *(float2*)(out + base0 + col) = v;
            }
            if (ok1) {
                __sincosf(med1 * dv, &s, &c);
                float2 v;
                v.x = acc[mf][nf][2] + bs0 + s;
                v.y = acc[mf][nf][3] + bs1 + c;
                *(float2*)(out + base1 + col) = v;
            }
        }
    }
}

extern "C" void kernel_launch(void* const* d_in, const int* in_sizes, int n_in,
                              void* d_out, int out_size) {
    const float* x    = (const float*)d_in[0];
    const float* ts   = (const float*)d_in[1];
    const float* w    = (const float*)d_in[2];
    const float* bias = (const float*)d_in[3];
    float* out = (float*)d_out;

    pack_w_kernel<<<256, 256>>>(w);

    dim3 grid(32, BN);   // 32 patch-tiles x 32 batches
    patch_encoder_kernel<<<grid, 128>>>(x, ts, bias, out);
}

// round 7
// speedup vs baseline: 1.4213x; 1.0564x over previous
#include <cuda_runtime.h>
#include <cuda_fp16.h>
#include <cstdint>

// Problem constants
#define BN 32
#define LN 32768
#define DN 128
#define PN 4095   // (L-K)/STRIDE + 1

// ---------------------------------------------------------------------------
// Pre-packed B (fp16), fragment-linear layout:
// half index = ((c*4 + ks)*16 + nb)*128 + l*4 + j*2 + e
//   c  = k64 chunk (0..7), ks = k16 step (0..3), nb = n-block of 8 (0..15),
//   l  = lane (0..31: g=l>>2, q=l&3), j = b0/b1, e = lo/hi half
// value = W[n][kg], n = nb*8+g, kg = c*64 + ks*16 + 2q + 8j + e
// W[n][kg] = conv_w[n*512 + (kg%32)*16 + (kg/32)]
// ---------------------------------------------------------------------------
__device__ __half g_Bh[65536];   // 128 KB

__global__ void pack_w_kernel(const float* __restrict__ w) {
    int idx = blockIdx.x * blockDim.x + threadIdx.x;  // 0..65535
    int e  = idx & 1;
    int j  = (idx >> 1) & 1;
    int l  = (idx >> 2) & 31;
    int nb = (idx >> 7) & 15;
    int ks = (idx >> 11) & 3;
    int c  = idx >> 13;
    int n  = nb * 8 + (l >> 2);
    int kg = c * 64 + ks * 16 + 2 * (l & 3) + 8 * j + e;
    g_Bh[idx] = __float2half_rn(w[n * 512 + (kg & 31) * 16 + (kg >> 5)]);
}

__device__ __forceinline__ uint32_t pack_h2(float x, float y) {
    uint32_t r;
    asm("{ .reg .f16 lo, hi;\n\t"
        "cvt.rn.f16.f32 lo, %1;\n\t"
        "cvt.rn.f16.f32 hi, %2;\n\t"
        "mov.b32 %0, {lo, hi}; }"
        : "=r"(r) : "f"(x), "f"(y));
    return r;
}

__device__ __forceinline__ void mma_f16(float c[4], const uint32_t a[4],
                                        uint32_t b0, uint32_t b1) {
    asm volatile(
        "mma.sync.aligned.m16n8k16.row.col.f32.f16.f16.f32 "
        "{%0,%1,%2,%3}, {%4,%5,%6,%7}, {%8,%9}, {%0,%1,%2,%3};\n"
        : "+f"(c[0]), "+f"(c[1]), "+f"(c[2]), "+f"(c[3])
        : "r"(a[0]), "r"(a[1]), "r"(a[2]), "r"(a[3]), "r"(b0), "r"(b1));
}

__device__ __forceinline__ uint32_t smem_u32(const void* p) {
    uint32_t a;
    asm("{ .reg .u64 t; cvta.to.shared.u64 t, %1; cvt.u32.u64 %0, t; }"
        : "=r"(a) : "l"(p));
    return a;
}

// A tile: 128 rows x 64 halfs (128B) padded to 144B pitch (conflict-free frags)
#define AROW 144
#define ATILE (128 * AROW)   // 18432 B per stage
#define BTILE 16384          // 128 n x 64 k halfs, fragment-linear

// CTA: 128 patches x 128 D, 128 threads = 4 warps, warp tile 64(m) x 64(n).
// K = 512 in 8 chunks of 64.  A and B double-buffered.
__global__ __launch_bounds__(128, 2) void patch_encoder_kernel(
    const float* __restrict__ x,     // (B, L, M)
    const float* __restrict__ ts,    // (B, L)
    const float* __restrict__ bias,  // (D,)
    float* __restrict__ out)         // (B, P, D)
{
    __shared__ __align__(16) unsigned char Abuf[2][ATILE];
    __shared__ __align__(16) unsigned char Bbuf[2][BTILE];
    __shared__ float meds[128];
    __shared__ float sbias[128];
    __shared__ float sdiv[64];

    const int tid  = threadIdx.x;
    const int b    = blockIdx.y;
    const int p0   = blockIdx.x * 128;
    const int wid  = tid >> 5;
    const int lane = tid & 31;
    const int wm   = wid & 1;     // m offset wm*64
    const int wn   = wid >> 1;    // n offset wn*64
    const int g    = lane >> 2;
    const int q    = lane & 3;

    if (tid < 128) {
        int p = p0 + tid;
        meds[tid]  = (p < PN) ? ts[(size_t)b * LN + p * 8 + 7] : 0.0f;
        sbias[tid] = bias[tid];
    }
    if (tid < 64)
        sdiv[tid] = expf((float)(2 * tid) * -0.07195578800731849f);

    float acc[4][8][4];
#pragma unroll
    for (int mf = 0; mf < 4; mf++)
#pragma unroll
        for (int nf = 0; nf < 8; nf++)
#pragma unroll
            for (int i = 0; i < 4; i++) acc[mf][nf][i] = 0.0f;

    const float* xbase = x + ((size_t)b * LN + (size_t)p0 * 8) * 32;
    const char*  gB    = (const char*)g_Bh;

    // A producer: ar = row sub-index (16 row-groups of 8 it), aj = float4 in half
    const int ar = tid >> 3;     // 0..15
    const int aj = tid & 7;      // 0..7

    float4 va[8];

    // load one half (32 floats/row) of chunk c_ into registers
#define LOAD_A(c_, h_)                                                        \
    do {                                                                      \
        _Pragma("unroll")                                                     \
        for (int it = 0; it < 8; it++) {                                      \
            int r = it * 16 + ar;                                             \
            va[it] = make_float4(0.f, 0.f, 0.f, 0.f);                         \
            if (p0 + r < PN)                                                  \
                va[it] = *(const float4*)(xbase + (size_t)r * 256 +           \
                                          (c_) * 64 + (h_) * 32 + aj * 4);    \
        }                                                                     \
    } while (0)

#define STS_A(buf_, h_)                                                       \
    do {                                                                      \
        _Pragma("unroll")                                                     \
        for (int it = 0; it < 8; it++) {                                      \
            int r = it * 16 + ar;                                             \
            uint32_t d = smem_u32(&Abuf[buf_][r * AROW + (h_) * 64 + aj * 8]); \
            uint32_t h0 = pack_h2(va[it].x, va[it].y);                        \
            uint32_t h1 = pack_h2(va[it].z, va[it].w);                        \
            asm volatile("st.shared.v2.b32 [%0], {%1,%2};"                    \
                         :: "r"(d), "r"(h0), "r"(h1));                        \
        }                                                                     \
    } while (0)

    // B: 16 KB per chunk, fragment-linear -> 8 x 16B cp.async per thread
#define CPASYNC_B(c_, st_)                                                    \
    do {                                                                      \
        _Pragma("unroll")                                                     \
        for (int i = 0; i < 8; i++) {                                         \
            int slot = i * 128 + tid;                                         \
            uint32_t d = smem_u32(&Bbuf[st_][slot * 16]);                     \
            const char* s = gB + (c_) * 16384 + slot * 16;                    \
            asm volatile("cp.async.cg.shared.global [%0], [%1], 16;"          \
                         :: "r"(d), "l"(s));                                  \
        }                                                                     \
        asm volatile("cp.async.commit_group;");                               \
    } while (0)

    // ---- prologue: chunk 0 ----
    LOAD_A(0, 0);
    CPASYNC_B(0, 0);
    STS_A(0, 0);
    LOAD_A(0, 1);
    STS_A(0, 1);
    asm volatile("cp.async.wait_group 0;" ::: "memory");
    __syncthreads();

    // fragment bases
    const uint32_t aBase = smem_u32(&Abuf[0][0]) + (wm * 64 + g) * AROW + q * 4;
    const uint32_t bBase = smem_u32(&Bbuf[0][0]) + (wn * 8) * 256 + lane * 8;

#define COMPUTE_KS(ks_)                                                       \
    do {                                                                      \
        uint32_t a[4][4];                                                     \
        _Pragma("unroll")                                                     \
        for (int mf = 0; mf < 4; mf++) {                                      \
            uint32_t ad = aB + mf * (16 * AROW) + (ks_) * 32;                 \
            asm volatile("ld.shared.b32 %0, [%1];"       : "=r"(a[mf][0]) : "r"(ad)); \
            asm volatile("ld.shared.b32 %0, [%1+1152];"  : "=r"(a[mf][1]) : "r"(ad)); \
            asm volatile("ld.shared.b32 %0, [%1+16];"    : "=r"(a[mf][2]) : "r"(ad)); \
            asm volatile("ld.shared.b32 %0, [%1+1168];"  : "=r"(a[mf][3]) : "r"(ad)); \
        }                                                                     \
        _Pragma("unroll")                                                     \
        for (int nf = 0; nf < 8; nf++) {                                      \
            uint32_t b0, b1;                                                  \
            uint32_t bd = bB + (ks_) * 4096 + nf * 256;                       \
            asm volatile("ld.shared.v2.b32 {%0,%1}, [%2];"                    \
                         : "=r"(b0), "=r"(b1) : "r"(bd));                     \
            _Pragma("unroll")                                                 \
            for (int mf = 0; mf < 4; mf++)                                    \
                mma_f16(acc[mf][nf], a[mf], b0, b1);                          \
        }                                                                     \
    } while (0)

    for (int c = 0; c < 8; c++) {
        const int cur = c & 1;
        const int nxt = cur ^ 1;
        const uint32_t aB = aBase + cur * ATILE;
        const uint32_t bB = bBase + cur * BTILE;

        if (c < 7) {
            LOAD_A(c + 1, 0);
            CPASYNC_B(c + 1, nxt);
        }

        COMPUTE_KS(0);
        COMPUTE_KS(1);

        if (c < 7) {
            STS_A(nxt, 0);
            LOAD_A(c + 1, 1);
        }

        COMPUTE_KS(2);
        COMPUTE_KS(3);

        if (c < 7) {
            STS_A(nxt, 1);
            asm volatile("cp.async.wait_group 0;" ::: "memory");
        }
        __syncthreads();
    }

    // ---- epilogue: + bias + positional encoding (fast sincos), write out ----
#pragma unroll
    for (int mf = 0; mf < 4; mf++) {
        int rr0 = wm * 64 + mf * 16 + g;
        int rr1 = rr0 + 8;
        float med0 = meds[rr0];
        float med1 = meds[rr1];
        bool ok0 = (p0 + rr0) < PN;
        bool ok1 = (p0 + rr1) < PN;
        size_t base0 = ((size_t)b * PN + (size_t)(p0 + rr0)) * DN;
        size_t base1 = ((size_t)b * PN + (size_t)(p0 + rr1)) * DN;
#pragma unroll
        for (int nf = 0; nf < 8; nf++) {
            int col = wn * 64 + nf * 8 + 2 * q;   // even
            float dv = sdiv[col >> 1];
            float bs0 = sbias[col];
            float bs1 = sbias[col + 1];
            float s, c;
            if (ok0) {
                __sincosf(med0 * dv, &s, &c);
                float2 v;
                v.x = acc[mf][nf][0] + bs0 + s;
                v.y = acc[mf][nf][1] + bs1 + c;
                *(float2*)(out + base0 + col) = v;
            }
            if (ok1) {
                __sincosf(med1 * dv, &s, &c);
                float2 v;
                v.x = acc[mf][nf][2] + bs0 + s;
                v.y = acc[mf][nf][3] + bs1 + c;
                *(float2*)(out + base1 + col) = v;
            }
        }
    }
}

extern "C" void kernel_launch(void* const* d_in, const int* in_sizes, int n_in,
                              void* d_out, int out_size) {
    const float* x    = (const float*)d_in[0];
    const float* ts   = (const float*)d_in[1];
    const float* w    = (const float*)d_in[2];
    const float* bias = (const float*)d_in[3];
    float* out = (float*)d_out;

    pack_w_kernel<<<256, 256>>>(w);

    dim3 grid(32, BN);   // 32 patch-tiles x 32 batches
    patch_encoder_kernel<<<grid, 128>>>(x, ts, bias, out);
}

// round 9
// speedup vs baseline: 1.4517x; 1.0214x over previous
#include <cuda_runtime.h>
#include <cuda_fp16.h>
#include <cstdint>

// Problem constants
#define BN 32
#define LN 32768
#define DN 128
#define PN 4095   // (L-K)/STRIDE + 1

// ---------------------------------------------------------------------------
// Pre-packed B (fp16), fragment-linear layout:
// half index = ((c*4 + ks)*16 + nb)*128 + l*4 + j*2 + e
// value = W[n][kg], n = nb*8+g, kg = c*64 + ks*16 + 2q + 8j + e
// W[n][kg] = conv_w[n*512 + (kg%32)*16 + (kg/32)]
// ---------------------------------------------------------------------------
__device__ __half g_Bh[65536];   // 128 KB

__global__ void pack_w_kernel(const float* __restrict__ w) {
    int idx = blockIdx.x * blockDim.x + threadIdx.x;  // 0..65535
    int e  = idx & 1;
    int j  = (idx >> 1) & 1;
    int l  = (idx >> 2) & 31;
    int nb = (idx >> 7) & 15;
    int ks = (idx >> 11) & 3;
    int c  = idx >> 13;
    int n  = nb * 8 + (l >> 2);
    int kg = c * 64 + ks * 16 + 2 * (l & 3) + 8 * j + e;
    g_Bh[idx] = __float2half_rn(w[n * 512 + (kg & 31) * 16 + (kg >> 5)]);
}

__device__ __forceinline__ uint32_t pack_h2(float x, float y) {
    uint32_t r;
    asm("{ .reg .f16 lo, hi;\n\t"
        "cvt.rn.f16.f32 lo, %1;\n\t"
        "cvt.rn.f16.f32 hi, %2;\n\t"
        "mov.b32 %0, {lo, hi}; }"
        : "=r"(r) : "f"(x), "f"(y));
    return r;
}

__device__ __forceinline__ void mma_f16(float c[4], const uint32_t a[4],
                                        uint32_t b0, uint32_t b1) {
    asm volatile(
        "mma.sync.aligned.m16n8k16.row.col.f32.f16.f16.f32 "
        "{%0,%1,%2,%3}, {%4,%5,%6,%7}, {%8,%9}, {%0,%1,%2,%3};\n"
        : "+f"(c[0]), "+f"(c[1]), "+f"(c[2]), "+f"(c[3])
        : "r"(a[0]), "r"(a[1]), "r"(a[2]), "r"(a[3]), "r"(b0), "r"(b1));
}

__device__ __forceinline__ uint32_t smem_u32(const void* p) {
    uint32_t a;
    asm("{ .reg .u64 t; cvta.to.shared.u64 t, %1; cvt.u32.u64 %0, t; }"
        : "=r"(a) : "l"(p));
    return a;
}

// A buffers: 4 of them (chunks 0-3), each 129 rows x 64 halfs, pitch 144B.
// Chunk c>=4 reads buffer c-4 shifted down one row (tile(c+4)[r] == tile(c)[r+1]).
#define AROW  144
#define ABUF  (129 * AROW)      // 18576 B
#define BTILE 16384             // fragment-linear B chunk

// SMEM offsets (dynamic shared)
#define OFF_A    0
#define OFF_B    (4 * ABUF)                  // 74304
#define OFF_MEDS (OFF_B + 2 * BTILE)         // 107040
#define OFF_BIAS (OFF_MEDS + 512)
#define OFF_DIV  (OFF_BIAS + 512)
#define SMEM_TOTAL (OFF_DIV + 256)           // 108320

// CTA: 128 patches x 128 D, 128 threads = 4 warps, warp tile 64(m) x 64(n).
// K = 512 in 8 chunks of 64; A loaded only for chunks 0-3 (overlap reuse).
__global__ __launch_bounds__(128, 2) void patch_encoder_kernel(
    const float* __restrict__ x,     // (B, L, M)
    const float* __restrict__ ts,    // (B, L)
    const float* __restrict__ bias,  // (D,)
    float* __restrict__ out)         // (B, P, D)
{
    extern __shared__ __align__(16) unsigned char smem[];
    const uint32_t sbase = smem_u32(smem);

    const int tid  = threadIdx.x;
    const int b    = blockIdx.y;
    const int p0   = blockIdx.x * 128;
    const int wid  = tid >> 5;
    const int lane = tid & 31;
    const int wm   = wid & 1;     // m offset wm*64
    const int wn   = wid >> 1;    // n offset wn*64
    const int g    = lane >> 2;
    const int q    = lane & 3;

    float* meds  = (float*)(smem + OFF_MEDS);
    float* sbias = (float*)(smem + OFF_BIAS);
    float* sdiv  = (float*)(smem + OFF_DIV);

    if (tid < 128) {
        int p = p0 + tid;
        meds[tid]  = (p < PN) ? ts[(size_t)b * LN + p * 8 + 7] : 0.0f;
        sbias[tid] = bias[tid];
    }
    if (tid < 64)
        sdiv[tid] = expf((float)(2 * tid) * -0.07195578800731849f);

    float acc[4][8][4];
#pragma unroll
    for (int mf = 0; mf < 4; mf++)
#pragma unroll
        for (int nf = 0; nf < 8; nf++)
#pragma unroll
            for (int i = 0; i < 4; i++) acc[mf][nf][i] = 0.0f;

    const float* xbase = x + ((size_t)b * LN + (size_t)p0 * 8) * 32;
    const char*  gB    = (const char*)g_Bh;

    // A producer coords: ar = row sub-index, aj = float4 within 32-float half
    const int ar = tid >> 3;     // 0..15
    const int aj = tid & 7;      // 0..7

    float4 va[8];

    // load half h_ (32 floats/row) of chunk c_ (rows 0-127).
    // Guard is READ validity (x bounds), not patch validity: the row for patch
    // index PN (=4095) is readable for chunks 0-3 (max float idx 1048575) and
    // is needed by the shifted reuse of chunks 4-7 for patch PN-1.
#define LOAD_A(c_, h_)                                                        \
    do {                                                                      \
        _Pragma("unroll")                                                     \
        for (int it = 0; it < 8; it++) {                                      \
            int r = it * 16 + ar;                                             \
            va[it] = make_float4(0.f, 0.f, 0.f, 0.f);                         \
            if (p0 + r < PN + 1)                                              \
                va[it] = *(const float4*)(xbase + (size_t)r * 256 +           \
                                          (c_) * 64 + (h_) * 32 + aj * 4);    \
        }                                                                     \
    } while (0)

#define STS_A(c_, h_)                                                         \
    do {                                                                      \
        _Pragma("unroll")                                                     \
        for (int it = 0; it < 8; it++) {                                      \
            int r = it * 16 + ar;                                             \
            uint32_t d = sbase + OFF_A + (c_) * ABUF + r * AROW +             \
                         (h_) * 64 + aj * 8;                                  \
            uint32_t h0 = pack_h2(va[it].x, va[it].y);                        \
            uint32_t h1 = pack_h2(va[it].z, va[it].w);                        \
            asm volatile("st.shared.v2.b32 [%0], {%1,%2};"                    \
                         :: "r"(d), "r"(h0), "r"(h1));                        \
        }                                                                     \
    } while (0)

    // B: 16 KB per chunk, fragment-linear -> 8 x 16B cp.async per thread
#define CPASYNC_B(c_, st_)                                                    \
    do {                                                                      \
        _Pragma("unroll")                                                     \
        for (int i = 0; i < 8; i++) {                                         \
            int slot = i * 128 + tid;                                         \
            uint32_t d = sbase + OFF_B + (st_) * BTILE + slot * 16;           \
            const char* s = gB + (c_) * 16384 + slot * 16;                    \
            asm volatile("cp.async.cg.shared.global [%0], [%1], 16;"          \
                         :: "r"(d), "l"(s));                                  \
        }                                                                     \
        asm volatile("cp.async.commit_group;");                               \
    } while (0)

    // ---- prologue: A chunk 0 (rows 0-127), extra row 128 of all 4 bufs, B0 ----
    LOAD_A(0, 0);
    CPASYNC_B(0, 0);
    STS_A(0, 0);
    LOAD_A(0, 1);
    STS_A(0, 1);
    if (tid < 64) {
        // row 128 (patch p0+128) for buffers 0..3; 4 floats per thread
        int bf   = tid >> 4;        // buffer (=chunk)
        int slot = tid & 15;        // float4 slot in 64-float row
        float4 v = make_float4(0.f, 0.f, 0.f, 0.f);
        if (p0 + 128 < PN + 1)
            v = *(const float4*)(xbase + (size_t)128 * 256 + bf * 64 + slot * 4);
        uint32_t d = sbase + OFF_A + bf * ABUF + 128 * AROW + slot * 8;
        uint32_t h0 = pack_h2(v.x, v.y);
        uint32_t h1 = pack_h2(v.z, v.w);
        asm volatile("st.shared.v2.b32 [%0], {%1,%2};"
                     :: "r"(d), "r"(h0), "r"(h1));
    }
    asm volatile("cp.async.wait_group 0;" ::: "memory");
    __syncthreads();

    const uint32_t aBase = sbase + OFF_A + (wm * 64 + g) * AROW + q * 4;
    const uint32_t bBase = sbase + OFF_B + (wn * 8) * 256 + lane * 8;

#define COMPUTE_KS(ks_)                                                       \
    do {                                                                      \
        uint32_t a[4][4];                                                     \
        _Pragma("unroll")                                                     \
        for (int mf = 0; mf < 4; mf++) {                                      \
            uint32_t ad = aB + mf * (16 * AROW) + (ks_) * 32;                 \
            asm volatile("ld.shared.b32 %0, [%1];"       : "=r"(a[mf][0]) : "r"(ad)); \
            asm volatile("ld.shared.b32 %0, [%1+1152];"  : "=r"(a[mf][1]) : "r"(ad)); \
            asm volatile("ld.shared.b32 %0, [%1+16];"    : "=r"(a[mf][2]) : "r"(ad)); \
            asm volatile("ld.shared.b32 %0, [%1+1168];"  : "=r"(a[mf][3]) : "r"(ad)); \
        }                                                                     \
        _Pragma("unroll")                                                     \
        for (int nf = 0; nf < 8; nf++) {                                      \
            uint32_t b0, b1;                                                  \
            uint32_t bd = bB + (ks_) * 4096 + nf * 256;                       \
            asm volatile("ld.shared.v2.b32 {%0,%1}, [%2];"                    \
                         : "=r"(b0), "=r"(b1) : "r"(bd));                     \
            _Pragma("unroll")                                                 \
            for (int mf = 0; mf < 4; mf++)                                    \
                mma_f16(acc[mf][nf], a[mf], b0, b1);                          \
        }                                                                     \
    } while (0)

#pragma unroll
    for (int c = 0; c < 8; c++) {
        const int buf    = c & 3;
        const int rowOff = c >> 2;          // chunks 4-7 read rows shifted by 1
        const uint32_t aB = aBase + buf * ABUF + rowOff * AROW;
        const uint32_t bB = bBase + (c & 1) * BTILE;

        if (c < 3) LOAD_A(c + 1, 0);
        if (c < 7) CPASYNC_B(c + 1, (c + 1) & 1);

        COMPUTE_KS(0);
        COMPUTE_KS(1);

        if (c < 3) {
            STS_A(c + 1, 0);
            LOAD_A(c + 1, 1);
        }

        COMPUTE_KS(2);
        COMPUTE_KS(3);

        if (c < 3) STS_A(c + 1, 1);
        if (c < 7) asm volatile("cp.async.wait_group 0;" ::: "memory");
        __syncthreads();
    }

    // ---- epilogue: + bias + positional encoding (fast sincos), write out ----
#pragma unroll
    for (int mf = 0; mf < 4; mf++) {
        int rr0 = wm * 64 + mf * 16 + g;
        int rr1 = rr0 + 8;
        float med0 = meds[rr0];
        float med1 = meds[rr1];
        bool ok0 = (p0 + rr0) < PN;
        bool ok1 = (p0 + rr1) < PN;
        size_t base0 = ((size_t)b * PN + (size_t)(p0 + rr0)) * DN;
        size_t base1 = ((size_t)b * PN + (size_t)(p0 + rr1)) * DN;
#pragma unroll
        for (int nf = 0; nf < 8; nf++) {
            int col = wn * 64 + nf * 8 + 2 * q;   // even
            float dv = sdiv[col >> 1];
            float bs0 = sbias[col];
            float bs1 = sbias[col + 1];
            float s, c;
            if (ok0) {
                __sincosf(med0 * dv, &s, &c);
                float2 v;
                v.x = acc[mf][nf][0] + bs0 + s;
                v.y = acc[mf][nf][1] + bs1 + c;
                *(float2*)(out + base0 + col) = v;
            }
            if (ok1) {
                __sincosf(med1 * dv, &s, &c);
                float2 v;
                v.x = acc[mf][nf][2] + bs0 + s;
                v.y = acc[mf][nf][3] + bs1 + c;
                *(float2*)(out + base1 + col) = v;
            }
        }
    }
}

extern "C" void kernel_launch(void* const* d_in, const int* in_sizes, int n_in,
                              void* d_out, int out_size) {
    const float* x    = (const float*)d_in[0];
    const float* ts   = (const float*)d_in[1];
    const float* w    = (const float*)d_in[2];
    const float* bias = (const float*)d_in[3];
    float* out = (float*)d_out;

    cudaFuncSetAttribute(patch_encoder_kernel,
                         cudaFuncAttributeMaxDynamicSharedMemorySize,
                         SMEM_TOTAL);

    pack_w_kernel<<<256, 256>>>(w);

    dim3 grid(32, BN);   // 32 patch-tiles x 32 batches
    patch_encoder_kernel<<<grid, 128, SMEM_TOTAL>>>(x, ts, bias, out);
}

// round 10
// speedup vs baseline: 1.5938x; 1.0979x over previous
#include <cuda_runtime.h>
#include <cuda_fp16.h>
#include <cstdint>

// Problem constants
#define BN 32
#define LN 32768
#define DN 128
#define PN 4095   // (L-K)/STRIDE + 1

// ---------------------------------------------------------------------------
// Pre-packed B (fp16), fragment-linear layout:
// half index = ((c*4 + ks)*16 + nb)*128 + l*4 + j*2 + e
// value = W[n][kg], n = nb*8+g, kg = c*64 + ks*16 + 2q + 8j + e
// W[n][kg] = conv_w[n*512 + (kg%32)*16 + (kg/32)]
// ---------------------------------------------------------------------------
__device__ __half g_Bh[65536];   // 128 KB

__global__ void pack_w_kernel(const float* __restrict__ w) {
    int idx = blockIdx.x * blockDim.x + threadIdx.x;  // 0..65535
    int e  = idx & 1;
    int j  = (idx >> 1) & 1;
    int l  = (idx >> 2) & 31;
    int nb = (idx >> 7) & 15;
    int ks = (idx >> 11) & 3;
    int c  = idx >> 13;
    int n  = nb * 8 + (l >> 2);
    int kg = c * 64 + ks * 16 + 2 * (l & 3) + 8 * j + e;
    g_Bh[idx] = __float2half_rn(w[n * 512 + (kg & 31) * 16 + (kg >> 5)]);
}

__device__ __forceinline__ uint32_t pack_h2(float x, float y) {
    uint32_t r;
    asm("{ .reg .f16 lo, hi;\n\t"
        "cvt.rn.f16.f32 lo, %1;\n\t"
        "cvt.rn.f16.f32 hi, %2;\n\t"
        "mov.b32 %0, {lo, hi}; }"
        : "=r"(r) : "f"(x), "f"(y));
    return r;
}

__device__ __forceinline__ void mma_f16(float c[4], const uint32_t a[4],
                                        uint32_t b0, uint32_t b1) {
    asm volatile(
        "mma.sync.aligned.m16n8k16.row.col.f32.f16.f16.f32 "
        "{%0,%1,%2,%3}, {%4,%5,%6,%7}, {%8,%9}, {%0,%1,%2,%3};\n"
        : "+f"(c[0]), "+f"(c[1]), "+f"(c[2]), "+f"(c[3])
        : "r"(a[0]), "r"(a[1]), "r"(a[2]), "r"(a[3]), "r"(b0), "r"(b1));
}

__device__ __forceinline__ uint32_t smem_u32(const void* p) {
    uint32_t a;
    asm("{ .reg .u64 t; cvta.to.shared.u64 t, %1; cvt.u32.u64 %0, t; }"
        : "=r"(a) : "l"(p));
    return a;
}

// A buffers: 4 (chunks 0-3), each 129 rows x 64 halfs, pitch 144B.
// Chunk c>=4 reads buffer c-4 shifted down one row.
#define AROW  144
#define ABUF  (129 * AROW)      // 18576 B
#define BTILE 16384             // fragment-linear B chunk

// SMEM offsets (dynamic shared)
#define OFF_A    0
#define OFF_B    (4 * ABUF)                  // 74304
#define OFF_MEDS (OFF_B + 2 * BTILE)         // 107040
#define OFF_BIAS (OFF_MEDS + 512)
#define OFF_DIV  (OFF_BIAS + 512)
#define SMEM_TOTAL (OFF_DIV + 256)           // 108320

// CTA: 128 patches x 128 D, 256 threads = 8 warps (2 m x 4 n),
// warp tile 64(m) x 32(n), acc = 64 regs/thread -> 2 CTAs/SM, 16 warps/SM.
// K = 512 in 8 chunks of 64; A loaded only for chunks 0-3 (overlap reuse).
__global__ __launch_bounds__(256, 2) void patch_encoder_kernel(
    const float* __restrict__ x,     // (B, L, M)
    const float* __restrict__ ts,    // (B, L)
    const float* __restrict__ bias,  // (D,)
    float* __restrict__ out)         // (B, P, D)
{
    extern __shared__ __align__(16) unsigned char smem[];
    const uint32_t sbase = smem_u32(smem);

    const int tid  = threadIdx.x;
    const int b    = blockIdx.y;
    const int p0   = blockIdx.x * 128;
    const int wid  = tid >> 5;
    const int lane = tid & 31;
    const int wm   = wid & 1;     // m offset wm*64
    const int wn   = wid >> 1;    // n offset wn*32  (0..3)
    const int g    = lane >> 2;
    const int q    = lane & 3;

    float* meds  = (float*)(smem + OFF_MEDS);
    float* sbias = (float*)(smem + OFF_BIAS);
    float* sdiv  = (float*)(smem + OFF_DIV);

    if (tid < 128) {
        int p = p0 + tid;
        meds[tid]  = (p < PN) ? ts[(size_t)b * LN + p * 8 + 7] : 0.0f;
        sbias[tid] = bias[tid];
    }
    if (tid >= 128 && tid < 192)
        sdiv[tid - 128] = expf((float)(2 * (tid - 128)) * -0.07195578800731849f);

    float acc[4][4][4];
#pragma unroll
    for (int mf = 0; mf < 4; mf++)
#pragma unroll
        for (int nf = 0; nf < 4; nf++)
#pragma unroll
            for (int i = 0; i < 4; i++) acc[mf][nf][i] = 0.0f;

    const float* xbase = x + ((size_t)b * LN + (size_t)p0 * 8) * 32;
    const char*  gB    = (const char*)g_Bh;

    // A producer coords: 1024 float4 slots / 256 threads = 4 per thread
    const int ar = tid >> 3;     // 0..31 (row sub-index)
    const int aj = tid & 7;      // float4 within 32-float half

    float4 va[4];

    // Guard is READ validity: row for patch PN is readable for chunks 0-3 and
    // needed by the shifted reuse (chunks 4-7) of patch PN-1.
#define LOAD_A(c_, h_)                                                        \
    do {                                                                      \
        _Pragma("unroll")                                                     \
        for (int it = 0; it < 4; it++) {                                      \
            int r = it * 32 + ar;                                             \
            va[it] = make_float4(0.f, 0.f, 0.f, 0.f);                         \
            if (p0 + r < PN + 1)                                              \
                va[it] = *(const float4*)(xbase + (size_t)r * 256 +           \
                                          (c_) * 64 + (h_) * 32 + aj * 4);    \
        }                                                                     \
    } while (0)

#define STS_A(c_, h_)                                                         \
    do {                                                                      \
        _Pragma("unroll")                                                     \
        for (int it = 0; it < 4; it++) {                                      \
            int r = it * 32 + ar;                                             \
            uint32_t d = sbase + OFF_A + (c_) * ABUF + r * AROW +             \
                         (h_) * 64 + aj * 8;                                  \
            uint32_t h0 = pack_h2(va[it].x, va[it].y);                        \
            uint32_t h1 = pack_h2(va[it].z, va[it].w);                        \
            asm volatile("st.shared.v2.b32 [%0], {%1,%2};"                    \
                         :: "r"(d), "r"(h0), "r"(h1));                        \
        }                                                                     \
    } while (0)

    // B: 16 KB per chunk, fragment-linear -> 4 x 16B cp.async per thread
#define CPASYNC_B(c_, st_)                                                    \
    do {                                                                      \
        _Pragma("unroll")                                                     \
        for (int i = 0; i < 4; i++) {                                         \
            int slot = i * 256 + tid;                                         \
            uint32_t d = sbase + OFF_B + (st_) * BTILE + slot * 16;           \
            const char* s = gB + (c_) * 16384 + slot * 16;                    \
            asm volatile("cp.async.cg.shared.global [%0], [%1], 16;"          \
                         :: "r"(d), "l"(s));                                  \
        }                                                                     \
        asm volatile("cp.async.commit_group;");                               \
    } while (0)

    // ---- prologue: A chunk 0, extra row 128 of all 4 bufs, B0 ----
    LOAD_A(0, 0);
    CPASYNC_B(0, 0);
    STS_A(0, 0);
    LOAD_A(0, 1);
    STS_A(0, 1);
    if (tid < 64) {
        int bf   = tid >> 4;        // buffer (=chunk)
        int slot = tid & 15;        // float4 slot in 64-float row
        float4 v = make_float4(0.f, 0.f, 0.f, 0.f);
        if (p0 + 128 < PN + 1)
            v = *(const float4*)(xbase + (size_t)128 * 256 + bf * 64 + slot * 4);
        uint32_t d = sbase + OFF_A + bf * ABUF + 128 * AROW + slot * 8;
        uint32_t h0 = pack_h2(v.x, v.y);
        uint32_t h1 = pack_h2(v.z, v.w);
        asm volatile("st.shared.v2.b32 [%0], {%1,%2};"
                     :: "r"(d), "r"(h0), "r"(h1));
    }
    asm volatile("cp.async.wait_group 0;" ::: "memory");
    __syncthreads();

    const uint32_t aBase = sbase + OFF_A + (wm * 64 + g) * AROW + q * 4;
    const uint32_t bBase = sbase + OFF_B + (wn * 4) * 256 + lane * 8;

#define COMPUTE_KS(ks_)                                                       \
    do {                                                                      \
        uint32_t a[4][4];                                                     \
        _Pragma("unroll")                                                     \
        for (int mf = 0; mf < 4; mf++) {                                      \
            uint32_t ad = aB + mf * (16 * AROW) + (ks_) * 32;                 \
            asm volatile("ld.shared.b32 %0, [%1];"       : "=r"(a[mf][0]) : "r"(ad)); \
            asm volatile("ld.shared.b32 %0, [%1+1152];"  : "=r"(a[mf][1]) : "r"(ad)); \
            asm volatile("ld.shared.b32 %0, [%1+16];"    : "=r"(a[mf][2]) : "r"(ad)); \
            asm volatile("ld.shared.b32 %0, [%1+1168];"  : "=r"(a[mf][3]) : "r"(ad)); \
        }                                                                     \
        _Pragma("unroll")                                                     \
        for (int nf = 0; nf < 4; nf++) {                                      \
            uint32_t b0, b1;                                                  \
            uint32_t bd = bB + (ks_) * 4096 + nf * 256;                       \
            asm volatile("ld.shared.v2.b32 {%0,%1}, [%2];"                    \
                         : "=r"(b0), "=r"(b1) : "r"(bd));                     \
            _Pragma("unroll")                                                 \
            for (int mf = 0; mf < 4; mf++)                                    \
                mma_f16(acc[mf][nf], a[mf], b0, b1);                          \
        }                                                                     \
    } while (0)

#pragma unroll
    for (int c = 0; c < 8; c++) {
        const int buf    = c & 3;
        const int rowOff = c >> 2;          // chunks 4-7 read rows shifted by 1
        const uint32_t aB = aBase + buf * ABUF + rowOff * AROW;
        const uint32_t bB = bBase + (c & 1) * BTILE;

        if (c < 3) LOAD_A(c + 1, 0);
        if (c < 7) CPASYNC_B(c + 1, (c + 1) & 1);

        COMPUTE_KS(0);
        COMPUTE_KS(1);

        if (c < 3) {
            STS_A(c + 1, 0);
            LOAD_A(c + 1, 1);
        }

        COMPUTE_KS(2);
        COMPUTE_KS(3);

        if (c < 3) STS_A(c + 1, 1);
        if (c < 7) asm volatile("cp.async.wait_group 0;" ::: "memory");
        __syncthreads();
    }

    // ---- epilogue: + bias + positional encoding (fast sincos), write out ----
#pragma unroll
    for (int mf = 0; mf < 4; mf++) {
        int rr0 = wm * 64 + mf * 16 + g;
        int rr1 = rr0 + 8;
        float med0 = meds[rr0];
        float med1 = meds[rr1];
        bool ok0 = (p0 + rr0) < PN;
        bool ok1 = (p0 + rr1) < PN;
        size_t base0 = ((size_t)b * PN + (size_t)(p0 + rr0)) * DN;
        size_t base1 = ((size_t)b * PN + (size_t)(p0 + rr1)) * DN;
#pragma unroll
        for (int nf = 0; nf < 4; nf++) {
            int col = wn * 32 + nf * 8 + 2 * q;   // even
            float dv = sdiv[col >> 1];
            float bs0 = sbias[col];
            float bs1 = sbias[col + 1];
            float s, c;
            if (ok0) {
                __sincosf(med0 * dv, &s, &c);
                float2 v;
                v.x = acc[mf][nf][0] + bs0 + s;
                v.y = acc[mf][nf][1] + bs1 + c;
                *(float2*)(out + base0 + col) = v;
            }
            if (ok1) {
                __sincosf(med1 * dv, &s, &c);
                float2 v;
                v.x = acc[mf][nf][2] + bs0 + s;
                v.y = acc[mf][nf][3] + bs1 + c;
                *(float2*)(out + base1 + col) = v;
            }
        }
    }
}

extern "C" void kernel_launch(void* const* d_in, const int* in_sizes, int n_in,
                              void* d_out, int out_size) {
    const float* x    = (const float*)d_in[0];
    const float* ts   = (const float*)d_in[1];
    const float* w    = (const float*)d_in[2];
    const float* bias = (const float*)d_in[3];
    float* out = (float*)d_out;

    cudaFuncSetAttribute(patch_encoder_kernel,
                         cudaFuncAttributeMaxDynamicSharedMemorySize,
                         SMEM_TOTAL);

    pack_w_kernel<<<256, 256>>>(w);

    dim3 grid(32, BN);   // 32 patch-tiles x 32 batches
    patch_encoder_kernel<<<grid, 256, SMEM_TOTAL>>>(x, ts, bias, out);
}

// round 13
// speedup vs baseline: 1.6365x; 1.0268x over previous
#include <cuda_runtime.h>
#include <cuda_fp16.h>
#include <cstdint>

// Problem constants
#define BN 32
#define LN 32768
#define DN 128
#define PN 4095   // (L-K)/STRIDE + 1

// ---------------------------------------------------------------------------
// Pre-packed B (fp16), fragment-linear layout:
// half index = ((c*4 + ks)*16 + nb)*128 + l*4 + j*2 + e
// value = W[n][kg], n = nb*8+g, kg = c*64 + ks*16 + 2q + 8j + e
// W[n][kg] = conv_w[n*512 + (kg%32)*16 + (kg/32)]
// ---------------------------------------------------------------------------
__device__ __half g_Bh[65536];   // 128 KB

__global__ void pack_w_kernel(const float* __restrict__ w) {
    int idx = blockIdx.x * blockDim.x + threadIdx.x;  // 0..65535
    int e  = idx & 1;
    int j  = (idx >> 1) & 1;
    int l  = (idx >> 2) & 31;
    int nb = (idx >> 7) & 15;
    int ks = (idx >> 11) & 3;
    int c  = idx >> 13;
    int n  = nb * 8 + (l >> 2);
    int kg = c * 64 + ks * 16 + 2 * (l & 3) + 8 * j + e;
    g_Bh[idx] = __float2half_rn(w[n * 512 + (kg & 31) * 16 + (kg >> 5)]);
}

__device__ __forceinline__ uint32_t pack_h2(float x, float y) {
    uint32_t r;
    asm("{ .reg .f16 lo, hi;\n\t"
        "cvt.rn.f16.f32 lo, %1;\n\t"
        "cvt.rn.f16.f32 hi, %2;\n\t"
        "mov.b32 %0, {lo, hi}; }"
        : "=r"(r) : "f"(x), "f"(y));
    return r;
}

__device__ __forceinline__ void mma_f16(float c[4], const uint32_t a[4],
                                        uint32_t b0, uint32_t b1) {
    asm volatile(
        "mma.sync.aligned.m16n8k16.row.col.f32.f16.f16.f32 "
        "{%0,%1,%2,%3}, {%4,%5,%6,%7}, {%8,%9}, {%0,%1,%2,%3};\n"
        : "+f"(c[0]), "+f"(c[1]), "+f"(c[2]), "+f"(c[3])
        : "r"(a[0]), "r"(a[1]), "r"(a[2]), "r"(a[3]), "r"(b0), "r"(b1));
}

__device__ __forceinline__ uint32_t smem_u32(const void* p) {
    uint32_t a;
    asm("{ .reg .u64 t; cvta.to.shared.u64 t, %1; cvt.u32.u64 %0, t; }"
        : "=r"(a) : "l"(p));
    return a;
}

// A buffers: 2, each 129 rows x 64 halfs, pitch 144B.
// Chunk pair (p, p+4) shares tile p: chunk p reads rows 0-127, p+4 rows 1-128.
#define AROW  144
#define ABUF  (129 * AROW)      // 18576 B
#define BTILE 16384             // fragment-linear B chunk

// SMEM offsets (dynamic shared)
#define OFF_A    0
#define OFF_B    (2 * ABUF)                  // 37152
#define OFF_MEDS (OFF_B + 4 * BTILE)         // 102688
#define OFF_BIAS (OFF_MEDS + 512)
#define OFF_DIV  (OFF_BIAS + 512)
#define SMEM_TOTAL (OFF_DIV + 256)           // 103968

// CTA: 128 patches x 128 D, 256 threads = 8 warps (2 m x 4 n),
// warp tile 64(m) x 32(n).  K = 512 as 4 pairs of chunks (c, c+4).
// A: 2 buffers, one tile per pair (overlap reuse).
// B: 4 stages; pair p uses stages (p%2)*2..+1, so pair p+2 ALIASES pair p.
// Therefore pair p+1's group is committed only in iteration p AFTER the
// barrier that retires pair p-1's readers (its stage aliases).
__global__ __launch_bounds__(256, 2) void patch_encoder_kernel(
    const float* __restrict__ x,     // (B, L, M)
    const float* __restrict__ ts,    // (B, L)
    const float* __restrict__ bias,  // (D,)
    float* __restrict__ out)         // (B, P, D)
{
    extern __shared__ __align__(16) unsigned char smem[];
    const uint32_t sbase = smem_u32(smem);

    const int tid  = threadIdx.x;
    const int b    = blockIdx.y;
    const int p0   = blockIdx.x * 128;
    const int wid  = tid >> 5;
    const int lane = tid & 31;
    const int wm   = wid & 1;     // m offset wm*64
    const int wn   = wid >> 1;    // n offset wn*32  (0..3)
    const int g    = lane >> 2;
    const int q    = lane & 3;

    float* meds  = (float*)(smem + OFF_MEDS);
    float* sbias = (float*)(smem + OFF_BIAS);
    float* sdiv  = (float*)(smem + OFF_DIV);

    if (tid < 128) {
        int p = p0 + tid;
        meds[tid]  = (p < PN) ? ts[(size_t)b * LN + p * 8 + 7] : 0.0f;
        sbias[tid] = bias[tid];
    }
    if (tid >= 128 && tid < 192)
        sdiv[tid - 128] = expf((float)(2 * (tid - 128)) * -0.07195578800731849f);

    float acc[4][4][4];
#pragma unroll
    for (int mf = 0; mf < 4; mf++)
#pragma unroll
        for (int nf = 0; nf < 4; nf++)
#pragma unroll
            for (int i = 0; i < 4; i++) acc[mf][nf][i] = 0.0f;

    const float* xbase = x + ((size_t)b * LN + (size_t)p0 * 8) * 32;
    const char*  gB    = (const char*)g_Bh;

    // A producer coords: 1024 float4 slots / 256 threads = 4 per thread
    const int ar = tid >> 3;     // 0..31 (row sub-index)
    const int aj = tid & 7;      // float4 within 32-float half

    float4 va[4];

    // READ-validity guard: the row for patch index PN is in-bounds for
    // chunks 0-3 and is needed (as row 128) by the shifted chunks 4-7.
#define LOAD_A(c_, h_)                                                        \
    do {                                                                      \
        _Pragma("unroll")                                                     \
        for (int it = 0; it < 4; it++) {                                      \
            int r = it * 32 + ar;                                             \
            va[it] = make_float4(0.f, 0.f, 0.f, 0.f);                         \
            if (p0 + r < PN + 1)                                              \
                va[it] = *(const float4*)(xbase + (size_t)r * 256 +           \
                                          (c_) * 64 + (h_) * 32 + aj * 4);    \
        }                                                                     \
    } while (0)

#define STS_A(buf_, h_)                                                       \
    do {                                                                      \
        _Pragma("unroll")                                                     \
        for (int it = 0; it < 4; it++) {                                      \
            int r = it * 32 + ar;                                             \
            uint32_t d = sbase + OFF_A + (buf_) * ABUF + r * AROW +           \
                         (h_) * 64 + aj * 8;                                  \
            uint32_t h0 = pack_h2(va[it].x, va[it].y);                        \
            uint32_t h1 = pack_h2(va[it].z, va[it].w);                        \
            asm volatile("st.shared.v2.b32 [%0], {%1,%2};"                    \
                         :: "r"(d), "r"(h0), "r"(h1));                        \
        }                                                                     \
    } while (0)

    // row 128 of tile c_ -> buffer buf_: 16 threads x one float4 (64 floats)
#define ROW128(c_, buf_)                                                      \
    do {                                                                      \
        if (tid < 16) {                                                       \
            float4 v = make_float4(0.f, 0.f, 0.f, 0.f);                       \
            if (p0 + 128 < PN + 1)                                            \
                v = *(const float4*)(xbase + (size_t)128 * 256 +              \
                                     (c_) * 64 + tid * 4);                    \
            uint32_t d = sbase + OFF_A + (buf_) * ABUF + 128 * AROW + tid * 8; \
            uint32_t h0 = pack_h2(v.x, v.y);                                  \
            uint32_t h1 = pack_h2(v.z, v.w);                                  \
            asm volatile("st.shared.v2.b32 [%0], {%1,%2};"                    \
                         :: "r"(d), "r"(h0), "r"(h1));                        \
        }                                                                     \
    } while (0)

    // B pair pp: chunk pp -> stage (pp&1)*2, chunk pp+4 -> stage (pp&1)*2+1.
    // One commit group per pair (32 KB = 8 x 16B per thread).
#define CPASYNC_B_PAIR(pp_)                                                   \
    do {                                                                      \
        const int s0_ = ((pp_) & 1) * 2;                                      \
        _Pragma("unroll")                                                     \
        for (int i = 0; i < 4; i++) {                                         \
            int slot = i * 256 + tid;                                         \
            uint32_t d = sbase + OFF_B + s0_ * BTILE + slot * 16;             \
            const char* s = gB + (pp_) * 16384 + slot * 16;                   \
            asm volatile("cp.async.cg.shared.global [%0], [%1], 16;"          \
                         :: "r"(d), "l"(s));                                  \
        }                                                                     \
        _Pragma("unroll")                                                     \
        for (int i = 0; i < 4; i++) {                                         \
            int slot = i * 256 + tid;                                         \
            uint32_t d = sbase + OFF_B + (s0_ + 1) * BTILE + slot * 16;       \
            const char* s = gB + ((pp_) + 4) * 16384 + slot * 16;             \
            asm volatile("cp.async.cg.shared.global [%0], [%1], 16;"          \
                         :: "r"(d), "l"(s));                                  \
        }                                                                     \
        asm volatile("cp.async.commit_group;");                               \
    } while (0)

    // ---- prologue: B pairs 0,1 in flight; A tile 0 into buffer 0 ----
    CPASYNC_B_PAIR(0);
    CPASYNC_B_PAIR(1);
    LOAD_A(0, 0);
    STS_A(0, 0);
    LOAD_A(0, 1);
    STS_A(0, 1);
    ROW128(0, 0);

    const uint32_t aBase = sbase + OFF_A + (wm * 64 + g) * AROW + q * 4;
    const uint32_t bBase = sbase + OFF_B + (wn * 4) * 256 + lane * 8;

#define COMPUTE_KS(aB_, bB_, ks_)                                             \
    do {                                                                      \
        uint32_t a[4][4];                                                     \
        _Pragma("unroll")                                                     \
        for (int mf = 0; mf < 4; mf++) {                                      \
            uint32_t ad = (aB_) + mf * (16 * AROW) + (ks_) * 32;              \
            asm volatile("ld.shared.b32 %0, [%1];"       : "=r"(a[mf][0]) : "r"(ad)); \
            asm volatile("ld.shared.b32 %0, [%1+1152];"  : "=r"(a[mf][1]) : "r"(ad)); \
            asm volatile("ld.shared.b32 %0, [%1+16];"    : "=r"(a[mf][2]) : "r"(ad)); \
            asm volatile("ld.shared.b32 %0, [%1+1168];"  : "=r"(a[mf][3]) : "r"(ad)); \
        }                                                                     \
        _Pragma("unroll")                                                     \
        for (int nf = 0; nf < 4; nf++) {                                      \
            uint32_t b0, b1;                                                  \
            uint32_t bd = (bB_) + (ks_) * 4096 + nf * 256;                    \
            asm volatile("ld.shared.v2.b32 {%0,%1}, [%2];"                    \
                         : "=r"(b0), "=r"(b1) : "r"(bd));                     \
            _Pragma("unroll")                                                 \
            for (int mf = 0; mf < 4; mf++)                                    \
                mma_f16(acc[mf][nf], a[mf], b0, b1);                          \
        }                                                                     \
    } while (0)

#pragma unroll
    for (int p = 0; p < 4; p++) {
        // Retire pair p's B group before reading it.
        // Iter 0: G1 may stay in flight (wait_group 1).  Iters 1-3: drain all.
        if (p == 0) asm volatile("cp.async.wait_group 1;" ::: "memory");
        else        asm volatile("cp.async.wait_group 0;" ::: "memory");
        __syncthreads();

        // Pair p+1's stages alias pair p-1, whose readers all retired before
        // the barrier above -> safe to commit its replacement copy NOW.
        if (p >= 1 && p + 1 <= 3) CPASYNC_B_PAIR(p + 1);

        const int buf = p & 1;
        const uint32_t aB0 = aBase + buf * ABUF;          // chunk p: rows 0-127
        const uint32_t aB1 = aB0 + AROW;                  // chunk p+4: rows 1-128
        const uint32_t bB0 = bBase + ((p & 1) * 2) * BTILE;
        const uint32_t bB1 = bB0 + BTILE;
        const int nbuf = buf ^ 1;

        // ---- chunk p ----
        if (p < 3) LOAD_A(p + 1, 0);
        COMPUTE_KS(aB0, bB0, 0);
        COMPUTE_KS(aB0, bB0, 1);
        if (p < 3) STS_A(nbuf, 0);
        COMPUTE_KS(aB0, bB0, 2);
        COMPUTE_KS(aB0, bB0, 3);

        // ---- chunk p+4 (shifted rows of same tile) ----
        if (p < 3) LOAD_A(p + 1, 1);
        COMPUTE_KS(aB1, bB1, 0);
        COMPUTE_KS(aB1, bB1, 1);
        if (p < 3) {
            STS_A(nbuf, 1);
            ROW128(p + 1, nbuf);
        }
        COMPUTE_KS(aB1, bB1, 2);
        COMPUTE_KS(aB1, bB1, 3);
    }

    // ---- epilogue: + bias + positional encoding (fast sincos), write out ----
#pragma unroll
    for (int mf = 0; mf < 4; mf++) {
        int rr0 = wm * 64 + mf * 16 + g;
        int rr1 = rr0 + 8;
        float med0 = meds[rr0];
        float med1 = meds[rr1];
        bool ok0 = (p0 + rr0) < PN;
        bool ok1 = (p0 + rr1) < PN;
        size_t base0 = ((size_t)b * PN + (size_t)(p0 + rr0)) * DN;
        size_t base1 = ((size_t)b * PN + (size_t)(p0 + rr1)) * DN;
#pragma unroll
        for (int nf = 0; nf < 4; nf++) {
            int col = wn * 32 + nf * 8 + 2 * q;   // even
            float dv = sdiv[col >> 1];
            float bs0 = sbias[col];
            float bs1 = sbias[col + 1];
            float s, c;
            if (ok0) {
                __sincosf(med0 * dv, &s, &c);
                float2 v;
                v.x = acc[mf][nf][0] + bs0 + s;
                v.y = acc[mf][nf][1] + bs1 + c;
                *(float2*)(out + base0 + col) = v;
            }
            if (ok1) {
                __sincosf(med1 * dv, &s, &c);
                float2 v;
                v.x = acc[mf][nf][2] + bs0 + s;
                v.y = acc[mf][nf][3] + bs1 + c;
                *(float2*)(out + base1 + col) = v;
            }
        }
    }
}

extern "C" void kernel_launch(void* const* d_in, const int* in_sizes, int n_in,
                              void* d_out, int out_size) {
    const float* x    = (const float*)d_in[0];
    const float* ts   = (const float*)d_in[1];
    const float* w    = (const float*)d_in[2];
    const float* bias = (const float*)d_in[3];
    float* out = (float*)d_out;

    cudaFuncSetAttribute(patch_encoder_kernel,
                         cudaFuncAttributeMaxDynamicSharedMemorySize,
                         SMEM_TOTAL);

    pack_w_kernel<<<256, 256>>>(w);

    dim3 grid(32, BN);   // 32 patch-tiles x 32 batches
    patch_encoder_kernel<<<grid, 256, SMEM_TOTAL>>>(x, ts, bias, out);
}